// round 17
// baseline (speedup 1.0000x reference)
#include <cuda_runtime.h>

// PlanarQuantMSE — four rows per CTA (grid=1024, TPB=512, two sequential
// row-pairs). R16's pair-body (best kernel, 32.9us) with setup/LUT amortized
// over 64KB and a 2.3-wave grid (smaller tail than R16's 4.6 waves).
// Quantizer: byte-LUT, exact boundary (lut[cell]->L; r>mid_sh[L]; c_sh[idx]).
// Output: [x_hat | indices-as-float] concatenated.

#define ROWS 4096
#define DIM  4096
#define TPB  512
#define VPT  2        // float4s per thread PER ROW (TPB*4*VPT == DIM)
#define NWARP (TPB / 32)
#define NPAIR 2       // row-pairs per CTA (4 rows total)
#define GRID (ROWS / (2 * NPAIR))
#define NCELL 1024
#define SCALEF 455.0f
// magic = 2^23*1.5 + 512 ; cell = bits(fma(v,S,magic)) - 0x4B400000 = round(v*S)+512
// |r| <= 1+3e-7 => cell in [57, 968]: no clamp needed.
#define MAGICF 12583424.0f
#define BITBASE 0x4B400000

__global__ __launch_bounds__(TPB, 3)
void pq_kernel(const float* __restrict__ x,
               const float* __restrict__ cent,
               const float* __restrict__ rot2,
               float* __restrict__ xhat,
               float* __restrict__ idxout)
{
    __shared__ unsigned char lut_sh[NCELL];
    __shared__ float  mid_sh[16];
    __shared__ float  c_sh[16];
    __shared__ int    tc_sh[15];
    __shared__ float  red[NPAIR][2][NWARP];
    __shared__ int    flag_sh;

    const int base_row = blockIdx.x * 2 * NPAIR;
    const int t  = threadIdx.x;
    const int w  = t >> 5;

    // ---- load pair 0 first (DRAM streams during setup) ----
    const float4* xr0 = (const float4*)(x + (size_t)base_row * DIM);
    const float4* xr1 = (const float4*)(x + (size_t)(base_row + 1) * DIM);
    float4 v0[VPT], v1[VPT];
#pragma unroll
    for (int k = 0; k < VPT; k++) v0[k] = xr0[t + k * TPB];
#pragma unroll
    for (int k = 0; k < VPT; k++) v1[k] = xr1[t + k * TPB];

    // ---- warp-0 setup: centroids, midpoints, cell ids, dup flag ----
    if (t < 16) {
        float cv = __ldg(&cent[t]);
        c_sh[t] = cv;
        float cn = __shfl_down_sync(0x0000ffffu, cv, 1);
        float mm = 0.5f * (cv + cn);
        int cell = __float_as_int(fmaf(mm, SCALEF, MAGICF)) - BITBASE;
        if (t < 15) { mid_sh[t] = mm; tc_sh[t] = cell; }
        else        { mid_sh[15] = 3.0e38f; }
        int celln = __shfl_down_sync(0x0000ffffu, cell, 1);
        unsigned dup = __ballot_sync(0x0000ffffu, (t < 14) && (cell == celln));
        if (t == 0) flag_sh = (dup != 0u) ? 1 : 0;
    }

    // ---- pair-0 sums of squares (interleaved = ILP) ----
    {
        float ss0 = 0.0f, ss1 = 0.0f;
#pragma unroll
        for (int k = 0; k < VPT; k++) {
            ss0 += v0[k].x * v0[k].x + v0[k].y * v0[k].y
                 + v0[k].z * v0[k].z + v0[k].w * v0[k].w;
            ss1 += v1[k].x * v1[k].x + v1[k].y * v1[k].y
                 + v1[k].z * v1[k].z + v1[k].w * v1[k].w;
        }
#pragma unroll
        for (int o = 16; o > 0; o >>= 1) {
            ss0 += __shfl_xor_sync(0xffffffffu, ss0, o);
            ss1 += __shfl_xor_sync(0xffffffffu, ss1, o);
        }
        if ((t & 31) == 0) { red[0][0][w] = ss0; red[0][1][w] = ss1; }
    }
    __syncthreads();                                   // barrier A: red[0]+tc

    // ---- byte-LUT build: threads 0..255, 4 cells each, packed STS.32 ----
    if (t < NCELL / 4) {
        const int cb = t * 4;
        int L0 = 0, L1 = 0, L2 = 0, L3 = 0;
#pragma unroll
        for (int j = 0; j < 15; j++) {
            int cj = tc_sh[j];
            L0 += (cj < cb)     ? 1 : 0;
            L1 += (cj < cb + 1) ? 1 : 0;
            L2 += (cj < cb + 2) ? 1 : 0;
            L3 += (cj < cb + 3) ? 1 : 0;
        }
        ((unsigned int*)lut_sh)[t] =
            (unsigned)L0 | ((unsigned)L1 << 8) | ((unsigned)L2 << 16) | ((unsigned)L3 << 24);
    }
    __syncthreads();                                   // barrier B: lut visible
    const int flag = flag_sh;

    const float4* rr = (const float4*)rot2;            // (c,s,c,s) per float4

#pragma unroll
    for (int p = 0; p < NPAIR; p++) {
        const int row0 = base_row + 2 * p;

        // per-thread norm finish from the 16 partials (broadcast LDS)
        float s20 = 0.0f, s21 = 0.0f;
#pragma unroll
        for (int q = 0; q < NWARP; q++) { s20 += red[p][0][q]; s21 += red[p][1][q]; }
        const float norm0 = fmaxf(sqrtf(s20), 1e-8f);
        const float inv0  = 1.0f / norm0;
        const float norm1 = fmaxf(sqrtf(s21), 1e-8f);
        const float inv1  = 1.0f / norm1;

#pragma unroll
        for (int rowi = 0; rowi < 2; rowi++) {
            const float norm = rowi ? norm1 : norm0;
            const float inv  = rowi ? inv1  : inv0;
            float4* xo = (float4*)(xhat   + (size_t)(row0 + rowi) * DIM);
            float4* io = (float4*)(idxout + (size_t)(row0 + rowi) * DIM);

#pragma unroll
            for (int k = 0; k < VPT; k++) {
                const int j = t + k * TPB;
                const float4 rs = __ldg(&rr[j]);
                const float4 xv = rowi ? v1[k] : v0[k];

                const float a0 = xv.x * inv, a1 = xv.y * inv;
                const float a2 = xv.z * inv, a3 = xv.w * inv;

                float r[4];
                r[0] = rs.x * a0 - rs.y * a1;
                r[1] = rs.y * a0 + rs.x * a1;
                r[2] = rs.z * a2 - rs.w * a3;
                r[3] = rs.w * a2 + rs.z * a3;

                float qv[4], f[4];
                if (!flag) {
#pragma unroll
                    for (int e = 0; e < 4; e++) {
                        int cell = __float_as_int(fmaf(r[e], SCALEF, MAGICF)) - BITBASE;
                        int L    = (int)lut_sh[cell];
                        int idx  = L + ((r[e] > mid_sh[L]) ? 1 : 0);
                        qv[e] = c_sh[idx];
                        f[e]  = (float)idx;
                    }
                } else {
#pragma unroll
                    for (int e = 0; e < 4; e++) {
                        int idx = 0;
#pragma unroll
                        for (int jj = 0; jj < 15; jj++) idx += (r[e] > mid_sh[jj]) ? 1 : 0;
                        qv[e] = c_sh[idx];
                        f[e]  = (float)idx;
                    }
                }

                float4 out;
                out.x = (rs.x * qv[0] + rs.y * qv[1]) * norm;
                out.y = (rs.x * qv[1] - rs.y * qv[0]) * norm;
                out.z = (rs.z * qv[2] + rs.w * qv[3]) * norm;
                out.w = (rs.z * qv[3] - rs.w * qv[2]) * norm;
                xo[j] = out;

                float4 fo;
                fo.x = f[0]; fo.y = f[1]; fo.z = f[2]; fo.w = f[3];
                io[j] = fo;
            }
        }

        // ---- load + reduce next pair, then one barrier ----
        if (p + 1 < NPAIR) {
            const int nrow = base_row + 2 * (p + 1);
            const float4* xn0 = (const float4*)(x + (size_t)nrow * DIM);
            const float4* xn1 = (const float4*)(x + (size_t)(nrow + 1) * DIM);
#pragma unroll
            for (int k = 0; k < VPT; k++) v0[k] = xn0[t + k * TPB];
#pragma unroll
            for (int k = 0; k < VPT; k++) v1[k] = xn1[t + k * TPB];

            float ss0 = 0.0f, ss1 = 0.0f;
#pragma unroll
            for (int k = 0; k < VPT; k++) {
                ss0 += v0[k].x * v0[k].x + v0[k].y * v0[k].y
                     + v0[k].z * v0[k].z + v0[k].w * v0[k].w;
                ss1 += v1[k].x * v1[k].x + v1[k].y * v1[k].y
                     + v1[k].z * v1[k].z + v1[k].w * v1[k].w;
            }
#pragma unroll
            for (int o = 16; o > 0; o >>= 1) {
                ss0 += __shfl_xor_sync(0xffffffffu, ss0, o);
                ss1 += __shfl_xor_sync(0xffffffffu, ss1, o);
            }
            if ((t & 31) == 0) { red[p + 1][0][w] = ss0; red[p + 1][1][w] = ss1; }
            __syncthreads();                           // barrier C: red[p+1]
        }
    }
}

extern "C" void kernel_launch(void* const* d_in, const int* in_sizes, int n_in,
                              void* d_out, int out_size) {
    const float* x = nullptr;
    const float* cent = nullptr;
    const float* rot2 = nullptr;
    for (int i = 0; i < n_in; i++) {
        if (in_sizes[i] == ROWS * DIM) x    = (const float*)d_in[i];
        else if (in_sizes[i] == 16)    cent = (const float*)d_in[i];
        else if (in_sizes[i] == 4096)  rot2 = (const float*)d_in[i];
    }

    float* xhat = (float*)d_out;
    float* idxf = xhat + (long long)ROWS * DIM;

    pq_kernel<<<GRID, TPB>>>(x, cent, rot2, xhat, idxf);
}